// round 6
// baseline (speedup 1.0000x reference)
#include <cuda_runtime.h>
#include <cuda_bf16.h>
#include <math.h>
#include <cstdint>

#define BATCH   32
#define HEADS   8
#define SEQ     512
#define DMODEL  1024
#define DHEAD   128
#define DCOL    18
#define BHS     (BATCH*HEADS)   // 256
#define BSD     ((size_t)BATCH*SEQ*DMODEL)   // 16777216

// ---------------- scratch (static device globals; no allocation) ----------------
__device__ __align__(256) __nv_bfloat16 g_xqh[BSD], g_xql[BSD];
__device__ __align__(256) __nv_bfloat16 g_xkh[BSD], g_xkl[BSD];
__device__ __align__(256) __nv_bfloat16 g_Whh[DMODEL*DMODEL], g_Whl[DMODEL*DMODEL];
__device__ __align__(256) __nv_bfloat16 g_Wvh[DMODEL*DMODEL], g_Wvl[DMODEL*DMODEL];
__device__ __align__(256) __nv_bfloat16 g_Woh[DMODEL*DMODEL], g_Wol[DMODEL*DMODEL];
__device__ __align__(256) __nv_bfloat16 g_fhh[BSD], g_fhl[BSD];   // f_head hi/lo [b,h,q,dh]
__device__ __align__(256) __nv_bfloat16 g_fth[BSD], g_ftl[BSD];   // f_tail hi/lo [b,h,k,dh]
__device__ __align__(256) float        g_fv [BSD];                 // f_v fp32 [b,h,k,dh]
__device__ __align__(256) __nv_bfloat16 g_ath[BSD], g_atl[BSD];    // attn hi/lo [b,q,h*dh]
__device__ __align__(256) float        g_adjm[(size_t)HEADS*SEQ*SEQ];

// ---------------- small helpers ----------------
__device__ __forceinline__ unsigned packbf(float f0, float f1) {   // f0 -> low half
    unsigned d;
    asm("cvt.rn.bf16x2.f32 %0, %1, %2;" : "=r"(d) : "f"(f1), "f"(f0));
    return d;
}
__device__ __forceinline__ float bf_lo(unsigned p) { return __uint_as_float(p << 16); }
__device__ __forceinline__ float bf_up(unsigned p) { return __uint_as_float(p & 0xFFFF0000u); }

__device__ __forceinline__ unsigned smem_u32(const void* p) {
    unsigned a;
    asm("{ .reg .u64 t; cvta.to.shared.u64 t, %1; cvt.u32.u64 %0, t; }" : "=r"(a) : "l"(p));
    return a;
}
__device__ __forceinline__ void cpa16s(unsigned dst, const void* src) {
    asm volatile("cp.async.ca.shared.global [%0], [%1], 16;" :: "r"(dst), "l"(src));
}
__device__ __forceinline__ void cpa_commit() { asm volatile("cp.async.commit_group;"); }
template<int N>
__device__ __forceinline__ void cpa_wait() { asm volatile("cp.async.wait_group %0;" :: "n"(N)); }

__device__ __forceinline__ void ldm4(unsigned& r0, unsigned& r1, unsigned& r2, unsigned& r3,
                                     unsigned addr) {
    asm volatile("ldmatrix.sync.aligned.m8n8.x4.shared.b16 {%0,%1,%2,%3}, [%4];"
                 : "=r"(r0), "=r"(r1), "=r"(r2), "=r"(r3) : "r"(addr));
}

__device__ __forceinline__ void mmabf(float* c, unsigned a0, unsigned a1, unsigned a2,
                                      unsigned a3, unsigned b0, unsigned b1) {
    asm volatile(
        "mma.sync.aligned.m16n8k16.row.col.f32.bf16.bf16.f32 "
        "{%0,%1,%2,%3}, {%4,%5,%6,%7}, {%8,%9}, {%0,%1,%2,%3};\n"
        : "+f"(c[0]), "+f"(c[1]), "+f"(c[2]), "+f"(c[3])
        : "r"(a0), "r"(a1), "r"(a2), "r"(a3), "r"(b0), "r"(b1));
}

__device__ __forceinline__ void cvt8(const float* f, unsigned* ph, unsigned* pl) {
#pragma unroll
    for (int j = 0; j < 4; j++) {
        unsigned h = packbf(f[2*j], f[2*j+1]);
        ph[j] = h;
        pl[j] = packbf(f[2*j] - bf_lo(h), f[2*j+1] - bf_up(h));
    }
}

// ---------------- fp32 -> bf16 hi/lo conversion (W selects destination) ----------------
template<int W>
__global__ void cvt_hilo(const float* __restrict__ src, int n4)
{
    __nv_bfloat16 *hi, *lo;
    if constexpr (W == 0) { hi = g_xqh; lo = g_xql; }
    else if constexpr (W == 1) { hi = g_xkh; lo = g_xkl; }
    else if constexpr (W == 2) { hi = g_Whh; lo = g_Whl; }
    else if constexpr (W == 3) { hi = g_Wvh; lo = g_Wvl; }
    else                       { hi = g_Woh; lo = g_Wol; }
    uint2* hu = reinterpret_cast<uint2*>(hi);
    uint2* lu = reinterpret_cast<uint2*>(lo);
    const float4* s4 = reinterpret_cast<const float4*>(src);
    for (int i = blockIdx.x * blockDim.x + threadIdx.x; i < n4; i += gridDim.x * blockDim.x) {
        float4 v = s4[i];
        unsigned h0 = packbf(v.x, v.y), h1 = packbf(v.z, v.w);
        unsigned l0 = packbf(v.x - bf_lo(h0), v.y - bf_up(h0));
        unsigned l1 = packbf(v.z - bf_lo(h1), v.w - bf_up(h1));
        hu[i] = make_uint2(h0, h1);
        lu[i] = make_uint2(l0, l1);
    }
}

// ---------------- adjacency: softmax(col_head @ col_tail^T, diag=0) ----------------
__global__ void adj_kernel(const float* __restrict__ col_head,
                           const float* __restrict__ col_tail)
{
    const int q = blockIdx.x;
    const int h = blockIdx.y;
    const int t = threadIdx.x;                 // 128 threads
    __shared__ float ch[DCOL];
    __shared__ float sred[4];

    if (t < DCOL) ch[t] = col_head[((size_t)h*SEQ + q)*DCOL + t];
    __syncthreads();

    float l[4];
#pragma unroll
    for (int i = 0; i < 4; i++) {
        const int k = t + i*128;
        const float* ct = col_tail + ((size_t)h*SEQ + k)*DCOL;
        float s = 0.f;
#pragma unroll
        for (int c = 0; c < DCOL; c++) s += ch[c]*ct[c];
        l[i] = (k == q) ? 0.f : s;
    }

    float mx = fmaxf(fmaxf(l[0],l[1]), fmaxf(l[2],l[3]));
#pragma unroll
    for (int o = 16; o; o >>= 1) mx = fmaxf(mx, __shfl_xor_sync(0xffffffffu, mx, o));
    if ((t & 31) == 0) sred[t >> 5] = mx;
    __syncthreads();
    mx = fmaxf(fmaxf(sred[0],sred[1]), fmaxf(sred[2],sred[3]));
    __syncthreads();

    float e[4]; float sum = 0.f;
#pragma unroll
    for (int i = 0; i < 4; i++) { e[i] = expf(l[i]-mx); sum += e[i]; }
#pragma unroll
    for (int o = 16; o; o >>= 1) sum += __shfl_xor_sync(0xffffffffu, sum, o);
    if ((t & 31) == 0) sred[t >> 5] = sum;
    __syncthreads();
    sum = sred[0]+sred[1]+sred[2]+sred[3];
    const float inv = 1.f/sum;

    float* dst = g_adjm + ((size_t)h*SEQ + q)*SEQ;
#pragma unroll
    for (int i = 0; i < 4; i++) {
        const int k = t + i*128;
        dst[k] = (1.f - e[i]*inv) * (-10000.f);
    }
}

// ---------------- mode epilogue: contiguous (n, n+1) pair ----------------
template<int MODE>
__device__ __forceinline__ void store_pair(float v0, float v1, int m, int n, int z,
    const float* __restrict__ bias, const float* __restrict__ aux,
    float* __restrict__ Cext)
{
    if constexpr (MODE == 0 || MODE == 1) {
        v0 = (v0 + bias[n]) * aux[n];
        v1 = (v1 + bias[n+1]) * aux[n+1];
        const int b = m >> 9, q = m & 511, h = n >> 7, dh = n & 127;
        const size_t idx = (((size_t)((b<<3)|h))*SEQ + q)*DHEAD + dh;  // even
        const unsigned ph = packbf(v0, v1);
        const unsigned pl = packbf(v0 - bf_lo(ph), v1 - bf_up(ph));
        __nv_bfloat16* dh_a = (MODE == 0) ? g_fhh : g_fth;
        __nv_bfloat16* dl_a = (MODE == 0) ? g_fhl : g_ftl;
        *reinterpret_cast<unsigned*>(&dh_a[idx]) = ph;
        *reinterpret_cast<unsigned*>(&dl_a[idx]) = pl;
    } else if constexpr (MODE == 2) {
        const int b = m >> 9, q = m & 511, h = n >> 7, dh = n & 127;
        float2 o; o.x = v0 + bias[n]; o.y = v1 + bias[n+1];
        *reinterpret_cast<float2*>(&g_fv[(((size_t)((b<<3)|h))*SEQ + q)*DHEAD + dh]) = o;
    } else if constexpr (MODE == 3) {
        const int h = z & 7;
        const size_t off = (size_t)m*SEQ + n;
        float2 am = *reinterpret_cast<const float2*>(&g_adjm[(size_t)h*SEQ*SEQ + off]);
        float2 o;
        o.x = v0 * 0.08838834764831845f + am.x;
        o.y = v1 * 0.08838834764831845f + am.y;
        *reinterpret_cast<float2*>(&Cext[(size_t)z*SEQ*SEQ + off]) = o;
    } else {
        float2 o; o.x = v0 + bias[n]; o.y = v1 + bias[n+1];
        *reinterpret_cast<float2*>(&Cext[(size_t)m*DMODEL + n]) = o;
    }
}

// ---------------- bf16 3-term ldmatrix GEMM: C = A[M,K] @ B[N,K]^T ----------------
#define LDK    40                 // padded smem row (bf16 elems), 80 bytes
#define TILEB  (128*LDK*2)        // 10240 B per tile
#define STAGEB (4*TILEB)          // Ah, Al, Bh, Bl
#define BFG_DSM (2*STAGEB)        // 81920 B

template<int MODE>
__global__ void __launch_bounds__(256, 2)
bf_gemm(const float* __restrict__ bias, const float* __restrict__ aux,
        float* __restrict__ Cext, int K)
{
    extern __shared__ char sm[];
    const unsigned sbase = smem_u32(sm);

    const int tid  = threadIdx.x;
    const int lane = tid & 31;
    const int warp = tid >> 5;
    const int wm   = warp >> 2, wn = warp & 3;
    const int z    = blockIdx.z;
    const int m0   = blockIdx.y * 128;
    const int n0   = blockIdx.x * 128;

    const __nv_bfloat16 *Ah, *Al, *Bh, *Bl;
    if constexpr (MODE == 0)      { Ah=g_xqh; Al=g_xql; Bh=g_Whh; Bl=g_Whl; }
    else if constexpr (MODE == 1) { Ah=g_xkh; Al=g_xkl; Bh=g_Whh; Bl=g_Whl; }
    else if constexpr (MODE == 2) { Ah=g_xkh; Al=g_xkl; Bh=g_Wvh; Bl=g_Wvl; }
    else if constexpr (MODE == 3) {
        Ah = g_fhh + (size_t)z*SEQ*DHEAD;  Al = g_fhl + (size_t)z*SEQ*DHEAD;
        Bh = g_fth + (size_t)z*SEQ*DHEAD;  Bl = g_ftl + (size_t)z*SEQ*DHEAD;
    } else {
        Ah = g_ath; Al = g_atl; Bh = g_Woh; Bl = g_Wol;
    }

    auto load_stage = [&](int st, int kt) {
        const unsigned sb = sbase + st*STAGEB;
#pragma unroll
        for (int i = 0; i < 8; i++) {
            const int idx  = tid + i*256;          // 0..2047 chunks
            const int tile = idx >> 9;             // 0:Ah 1:Al 2:Bh 3:Bl
            const int r    = (idx >> 2) & 127;
            const int c    = idx & 3;              // 16B chunk within 64B row
            const __nv_bfloat16* s = (tile == 0) ? Ah : (tile == 1) ? Al :
                                     (tile == 2) ? Bh : Bl;
            const int rg = ((tile < 2) ? m0 : n0) + r;
            cpa16s(sb + tile*TILEB + r*(LDK*2) + c*16,
                   s + (size_t)rg*K + kt + c*8);
        }
    };

    float acc[4][4][4];
#pragma unroll
    for (int i = 0; i < 4; i++)
#pragma unroll
        for (int j = 0; j < 4; j++)
#pragma unroll
            for (int f = 0; f < 4; f++) acc[i][j][f] = 0.f;

    // ldmatrix lane geometry
    const int rowA = (lane & 7) + ((lane >> 3) & 1) * 8;
    const int colA = ((lane >> 4) & 1) * 8;
    const int rowB = (lane & 7) + ((lane >> 4) & 1) * 8;
    const int colB = ((lane >> 3) & 1) * 8;

    const int iters = K >> 5;
    load_stage(0, 0);
    cpa_commit();

    for (int it = 0; it < iters; ++it) {
        const int cur = it & 1;
        if (it + 1 < iters) { load_stage(cur ^ 1, (it + 1) << 5); cpa_commit(); cpa_wait<1>(); }
        else                { cpa_wait<0>(); }
        __syncthreads();

        const unsigned sb  = sbase + cur*STAGEB;
        const unsigned aAh = sb + (wm*64 + rowA)*(LDK*2) + colA*2;
        const unsigned aAl = aAh + TILEB;
        const unsigned aBh = sb + 2*TILEB + (wn*32 + rowB)*(LDK*2) + colB*2;
        const unsigned aBl = aBh + TILEB;

#pragma unroll
        for (int ks = 0; ks < 2; ks++) {
            const unsigned ko = ks*32;   // 16 bf16 = 32 bytes
            unsigned bh[4][2], bl[4][2];
#pragma unroll
            for (int p = 0; p < 2; p++) {
                unsigned r0, r1, r2, r3;
                ldm4(r0, r1, r2, r3, aBh + p*16*(LDK*2) + ko);
                bh[2*p][0]=r0; bh[2*p][1]=r1; bh[2*p+1][0]=r2; bh[2*p+1][1]=r3;
                ldm4(r0, r1, r2, r3, aBl + p*16*(LDK*2) + ko);
                bl[2*p][0]=r0; bl[2*p][1]=r1; bl[2*p+1][0]=r2; bl[2*p+1][1]=r3;
            }
#pragma unroll
            for (int mt = 0; mt < 4; mt++) {
                unsigned a[4], al_[4];
                ldm4(a[0], a[1], a[2], a[3],     aAh + mt*16*(LDK*2) + ko);
                ldm4(al_[0], al_[1], al_[2], al_[3], aAl + mt*16*(LDK*2) + ko);
#pragma unroll
                for (int nt = 0; nt < 4; nt++) {
                    mmabf(acc[mt][nt], a[0],a[1],a[2],a[3],     bh[nt][0], bh[nt][1]);
                    mmabf(acc[mt][nt], a[0],a[1],a[2],a[3],     bl[nt][0], bl[nt][1]);
                    mmabf(acc[mt][nt], al_[0],al_[1],al_[2],al_[3], bh[nt][0], bh[nt][1]);
                }
            }
        }
        __syncthreads();
    }

    const int lr2 = lane >> 2;
    const int lc2 = (lane & 3) << 1;
#pragma unroll
    for (int mt = 0; mt < 4; mt++)
#pragma unroll
        for (int nt = 0; nt < 4; nt++) {
            const int mb = m0 + wm*64 + mt*16 + lr2;
            const int nb = n0 + wn*32 + nt*8 + lc2;
            store_pair<MODE>(acc[mt][nt][0], acc[mt][nt][1], mb,   nb, z, bias, aux, Cext);
            store_pair<MODE>(acc[mt][nt][2], acc[mt][nt][3], mb+8, nb, z, bias, aux, Cext);
        }
}

// ---------------- fused softmax + P @ V ----------------
// fr[z] holds raw logits on entry. This kernel: (pass 1) per-row max + sumexp,
// (mainloop) converts logits to probabilities in registers, writes P back to fr
// in place, packs P as bf16 hi/lo, and accumulates P @ V into g_ath/g_atl.
__global__ void __launch_bounds__(256, 2)
gemm_sm_pv(float* __restrict__ fr, int K)
{
    constexpr int BM = 128, PPAD = 12;
    __shared__ __align__(16) unsigned pAh[BM][PPAD];
    __shared__ __align__(16) unsigned pAl[BM][PPAD];
    __shared__ __align__(16) unsigned pBh[128][PPAD];
    __shared__ __align__(16) unsigned pBl[128][PPAD];
    __shared__ float sm_m[BM];
    __shared__ float sm_inv[BM];

    const int tid  = threadIdx.x;
    const int lane = tid & 31;
    const int warp = tid >> 5;
    const int wm   = warp >> 2, wn = warp & 3;
    const int lr   = lane >> 2, lc = lane & 3;
    const int z    = blockIdx.z;

    float* A        = fr + (size_t)z*SEQ*SEQ;
    const float* Bp = g_fv + (size_t)z*SEQ*DHEAD;

    const int m0 = blockIdx.y * BM;

    const int arow  = tid >> 1;
    const int akoff = (tid & 1) << 3;
    const int bn    = tid & 127;
    const int bhalf = tid >> 7;

    float fa[8], fb[8];

    auto ldg_stage = [&](int kt) {
        const float* ap = A + (size_t)(m0 + arow)*K + kt + akoff;
        float4 v0 = *reinterpret_cast<const float4*>(ap);
        float4 v1 = *reinterpret_cast<const float4*>(ap + 4);
        fa[0]=v0.x; fa[1]=v0.y; fa[2]=v0.z; fa[3]=v0.w;
        fa[4]=v1.x; fa[5]=v1.y; fa[6]=v1.z; fa[7]=v1.w;
#pragma unroll
        for (int j = 0; j < 8; j++)
            fb[j] = Bp[(size_t)(kt + 8*bhalf + j)*DHEAD + bn];
    };

    // prefetch chunk 0 (reads complete before any in-place P writes)
    ldg_stage(0);

    // ---- pass 1: per-row max and sum of exp (warp handles 16 rows) ----
    {
        const int r0 = warp * 16;
        for (int rr = 0; rr < 16; rr++) {
            const int r = r0 + rr;
            const float4* rp = reinterpret_cast<const float4*>(A + (size_t)(m0 + r)*SEQ);
            float4 v0 = rp[lane], v1 = rp[lane+32], v2 = rp[lane+64], v3 = rp[lane+96];
            float mx = fmaxf(fmaxf(fmaxf(v0.x,v0.y), fmaxf(v0.z,v0.w)),
                      fmaxf(fmaxf(fmaxf(v1.x,v1.y), fmaxf(v1.z,v1.w)),
                      fmaxf(fmaxf(fmaxf(v2.x,v2.y), fmaxf(v2.z,v2.w)),
                            fmaxf(fmaxf(v3.x,v3.y), fmaxf(v3.z,v3.w)))));
#pragma unroll
            for (int o = 16; o; o >>= 1) mx = fmaxf(mx, __shfl_xor_sync(0xffffffffu, mx, o));
            float s = __expf(v0.x-mx)+__expf(v0.y-mx)+__expf(v0.z-mx)+__expf(v0.w-mx)
                    + __expf(v1.x-mx)+__expf(v1.y-mx)+__expf(v1.z-mx)+__expf(v1.w-mx)
                    + __expf(v2.x-mx)+__expf(v2.y-mx)+__expf(v2.z-mx)+__expf(v2.w-mx)
                    + __expf(v3.x-mx)+__expf(v3.y-mx)+__expf(v3.z-mx)+__expf(v3.w-mx);
#pragma unroll
            for (int o = 16; o; o >>= 1) s += __shfl_xor_sync(0xffffffffu, s, o);
            if (lane == 0) { sm_m[r] = mx; sm_inv[r] = 1.f/s; }
        }
    }
    __syncthreads();

    float acc[4][4][4];
#pragma unroll
    for (int i = 0; i < 4; i++)
#pragma unroll
        for (int j = 0; j < 4; j++)
#pragma unroll
            for (int f = 0; f < 4; f++) acc[i][j][f] = 0.f;

    const int iters = K / 16;

    for (int it = 0; it < iters; ++it) {
        __syncthreads();
        {
            // logits -> probabilities for this chunk
            const float mr = sm_m[arow];
            const float ir = sm_inv[arow];
#pragma unroll
            for (int j = 0; j < 8; j++) fa[j] = __expf(fa[j] - mr) * ir;

            // write P back in place (fr_graph output)
            float* ap = A + (size_t)(m0 + arow)*K + it*16 + akoff;
            *reinterpret_cast<float4*>(ap)     = make_float4(fa[0], fa[1], fa[2], fa[3]);
            *reinterpret_cast<float4*>(ap + 4) = make_float4(fa[4], fa[5], fa[6], fa[7]);

            unsigned ph[4], pl[4];
            cvt8(fa, ph, pl);
            *reinterpret_cast<uint4*>(&pAh[arow][akoff >> 1]) = make_uint4(ph[0],ph[1],ph[2],ph[3]);
            *reinterpret_cast<uint4*>(&pAl[arow][akoff >> 1]) = make_uint4(pl[0],pl[1],pl[2],pl[3]);
            cvt8(fb, ph, pl);
            *reinterpret_cast<uint4*>(&pBh[bn][4*bhalf]) = make_uint4(ph[0],ph[1],ph[2],ph[3]);
            *reinterpret_cast<uint4*>(&pBl[bn][4*bhalf]) = make_uint4(pl[0],pl[1],pl[2],pl[3]);
        }
        __syncthreads();

        if (it + 1 < iters) ldg_stage((it + 1) * 16);

        uint2 a0[4], a1[4], b_h[4], b_l[4];
#pragma unroll
        for (int mt = 0; mt < 4; mt++) {
            const int r = wm*64 + mt*16 + lr;
            a0[mt] = *reinterpret_cast<const uint2*>(&pAh[r  ][2*lc]);
            a1[mt] = *reinterpret_cast<const uint2*>(&pAh[r+8][2*lc]);
        }
#pragma unroll
        for (int nt = 0; nt < 4; nt++) {
            const int c = wn*32 + nt*8 + lr;
            b_h[nt] = *reinterpret_cast<const uint2*>(&pBh[c][2*lc]);
            b_l[nt] = *reinterpret_cast<const uint2*>(&pBl[c][2*lc]);
        }
#pragma unroll
        for (int mt = 0; mt < 4; mt++)
#pragma unroll
            for (int nt = 0; nt < 4; nt++) {
                mmabf(acc[mt][nt], a0[mt].x, a1[mt].x, a0[mt].y, a1[mt].y, b_h[nt].x, b_h[nt].y);
                mmabf(acc[mt][nt], a0[mt].x, a1[mt].x, a0[mt].y, a1[mt].y, b_l[nt].x, b_l[nt].y);
            }
#pragma unroll
        for (int mt = 0; mt < 4; mt++) {
            const int r = wm*64 + mt*16 + lr;
            a0[mt] = *reinterpret_cast<const uint2*>(&pAl[r  ][2*lc]);
            a1[mt] = *reinterpret_cast<const uint2*>(&pAl[r+8][2*lc]);
        }
#pragma unroll
        for (int mt = 0; mt < 4; mt++)
#pragma unroll
            for (int nt = 0; nt < 4; nt++)
                mmabf(acc[mt][nt], a0[mt].x, a1[mt].x, a0[mt].y, a1[mt].y, b_h[nt].x, b_h[nt].y);
    }

    // epilogue: emit attn hi/lo bf16 pairs
    const int b = z >> 3, h = z & 7;
    const int lc2 = (lane & 3) << 1;
#pragma unroll
    for (int mt = 0; mt < 4; mt++)
#pragma unroll
        for (int nt = 0; nt < 4; nt++) {
            const int mb = m0 + wm*64 + mt*16 + lr;
            const int nb = wn*32 + nt*8 + lc2;
#pragma unroll
            for (int hh = 0; hh < 2; hh++) {
                const float v0 = acc[mt][nt][hh*2+0];
                const float v1 = acc[mt][nt][hh*2+1];
                const size_t idx = ((size_t)(b*SEQ + mb + hh*8))*DMODEL + h*DHEAD + nb;
                const unsigned ph = packbf(v0, v1);
                const unsigned pl = packbf(v0 - bf_lo(ph), v1 - bf_up(ph));
                *reinterpret_cast<unsigned*>(&g_ath[idx]) = ph;
                *reinterpret_cast<unsigned*>(&g_atl[idx]) = pl;
            }
        }
}

// ---------------- launch ----------------
extern "C" void kernel_launch(void* const* d_in, const int* in_sizes, int n_in,
                              void* d_out, int out_size)
{
    const float* x_q      = (const float*)d_in[0];
    const float* x_kv     = (const float*)d_in[1];
    const float* W_head_w = (const float*)d_in[2];
    const float* W_head_b = (const float*)d_in[3];
    const float* W_v_w    = (const float*)d_in[4];
    const float* W_v_b    = (const float*)d_in[5];
    const float* W_out_w  = (const float*)d_in[6];
    const float* W_out_b  = (const float*)d_in[7];
    const float* rel_emb  = (const float*)d_in[8];
    const float* col_head = (const float*)d_in[9];
    const float* col_tail = (const float*)d_in[10];

    float* out_x  = (float*)d_out;                          // [32,512,1024]
    float* out_fr = out_x + (size_t)BATCH*SEQ*DMODEL;       // [256,512,512]

    static bool attr_done = false;
    if (!attr_done) {
        cudaFuncSetAttribute(bf_gemm<0>, cudaFuncAttributeMaxDynamicSharedMemorySize, BFG_DSM);
        cudaFuncSetAttribute(bf_gemm<1>, cudaFuncAttributeMaxDynamicSharedMemorySize, BFG_DSM);
        cudaFuncSetAttribute(bf_gemm<2>, cudaFuncAttributeMaxDynamicSharedMemorySize, BFG_DSM);
        cudaFuncSetAttribute(bf_gemm<3>, cudaFuncAttributeMaxDynamicSharedMemorySize, BFG_DSM);
        cudaFuncSetAttribute(bf_gemm<5>, cudaFuncAttributeMaxDynamicSharedMemorySize, BFG_DSM);
        attr_done = true;
    }

    // 0) pre-convert inputs to bf16 hi/lo
    cvt_hilo<0><<<2048, 256>>>(x_q,      (int)(BSD/4));
    cvt_hilo<1><<<2048, 256>>>(x_kv,     (int)(BSD/4));
    cvt_hilo<2><<<1024, 256>>>(W_head_w, DMODEL*DMODEL/4);
    cvt_hilo<3><<<1024, 256>>>(W_v_w,    DMODEL*DMODEL/4);
    cvt_hilo<4><<<1024, 256>>>(W_out_w,  DMODEL*DMODEL/4);

    // 1) learned column topology mask
    adj_kernel<<<dim3(SEQ, HEADS), 128>>>(col_head, col_tail);

    // 2) projections
    bf_gemm<0><<<dim3(8, 128), 256, BFG_DSM>>>(W_head_b, rel_emb, nullptr, DMODEL);
    bf_gemm<1><<<dim3(8, 128), 256, BFG_DSM>>>(W_head_b, rel_emb, nullptr, DMODEL);
    bf_gemm<2><<<dim3(8, 128), 256, BFG_DSM>>>(W_v_b,    nullptr, nullptr, DMODEL);

    // 3) scores + mask -> fr region of d_out (raw logits)
    bf_gemm<3><<<dim3(4, 4, BHS), 256, BFG_DSM>>>(nullptr, nullptr, out_fr, DHEAD);

    // 4+5) fused softmax + P @ V -> fr gets final probabilities, attn hi/lo produced
    gemm_sm_pv<<<dim3(1, 4, BHS), 256>>>(out_fr, SEQ);

    // 6) output projection
    bf_gemm<5><<<dim3(8, 128), 256, BFG_DSM>>>(W_out_b, nullptr, out_x, DMODEL);
}